// round 5
// baseline (speedup 1.0000x reference)
#include <cuda_runtime.h>
#include <cuda_bf16.h>
#include <math.h>

#define NN    40000
#define RR    4
#define DIN   128
#define DOUT  40
#define EE    480000
#define XDIM  132      // R + DIN
#define NB    384      // 3 effective roles * 128

// ---------------- scratch (device globals; no allocation allowed) -------------
__device__ __align__(256) float g_feats[NN * DIN];     // 20.5 MB
__device__ __align__(256) float g_lin[NN * NB];        // 61.4 MB
__device__ __align__(256) float g_m[NN * DIN];         // 20.5 MB
__device__ __align__(256) float g_ssum[NN * DIN];      // 20.5 MB
__device__ __align__(256) float g_cnt[NN];
__device__ __align__(256) float g_cat[NN * 2 * DIN];   // 41 MB
__device__ __align__(256) float g_z[NN * DIN];
__device__ __align__(256) float g_logits[NN * DOUT];
__device__ __align__(256) float g_Bm[DIN * NB];        // packed Wm[l] -> (128,384)
__device__ __align__(256) float g_Ba[2 * DIN * NB];    // packed Wa[l] -> (256,384)

// ---------------- small helper kernels ----------------------------------------

__global__ void init_feats_k(const float* __restrict__ x) {
    int idx = blockIdx.x * blockDim.x + threadIdx.x;
    if (idx >= NN * DIN) return;
    int n = idx >> 7, i = idx & 127;
    g_feats[idx] = x[n * XDIM + RR + i];
}

// degree count: depends only on dst, identical for both layers -> compute once
__global__ void zero_cnt_k() {
    int idx = blockIdx.x * blockDim.x + threadIdx.x;
    if (idx < NN) g_cnt[idx] = 0.f;
}

__global__ void count_deg_k(const int* __restrict__ dst) {
    int e = blockIdx.x * blockDim.x + threadIdx.x;
    if (e >= EE) return;
    atomicAdd(&g_cnt[dst[e]], 1.0f);
}

// pack Wm[l] (R,128,128) -> B (128, 384), B[k][r*128+o] = Wm[r][k][o], r<3
__global__ void pack_Bm_k(const float* __restrict__ Wm_l) {
    int idx = blockIdx.x * blockDim.x + threadIdx.x;
    if (idx >= 3 * DIN * DIN) return;
    int r = idx / (DIN * DIN);
    int rem = idx - r * DIN * DIN;
    int k = rem >> 7, o = rem & 127;
    g_Bm[k * NB + r * DIN + o] = Wm_l[r * DIN * DIN + k * DIN + o];
}

// pack Wa[l] (R,256,128) -> B (256, 384)
__global__ void pack_Ba_k(const float* __restrict__ Wa_l) {
    int idx = blockIdx.x * blockDim.x + threadIdx.x;
    if (idx >= 3 * 2 * DIN * DIN) return;
    int r = idx / (2 * DIN * DIN);
    int rem = idx - r * 2 * DIN * DIN;
    int k = rem >> 7, o = rem & 127;
    g_Ba[k * NB + r * DIN + o] = Wa_l[r * 2 * DIN * DIN + k * DIN + o];
}

// ---------------- SGEMM: C(M,Nn) = A(M,K) * B(K,Nn) (+bias) -------------------
// BM=BN=64, BK=8, 256 threads, 4x4 register tile per thread.
__global__ void __launch_bounds__(256) sgemm_k(
    const float* __restrict__ A, const float* __restrict__ B,
    float* __restrict__ C, const float* __restrict__ bias,
    int M, int K, int Nn)
{
    __shared__ float As[8][64];
    __shared__ float Bs[8][64];
    const int bm = blockIdx.y * 64;
    const int bn = blockIdx.x * 64;
    const int tid  = threadIdx.x;
    const int tcol = tid & 15;   // 16 thread-cols
    const int trow = tid >> 4;   // 16 thread-rows

    float acc[4][4];
#pragma unroll
    for (int i = 0; i < 4; i++)
#pragma unroll
        for (int j = 0; j < 4; j++) acc[i][j] = 0.f;

    for (int k0 = 0; k0 < K; k0 += 8) {
#pragma unroll
        for (int t = tid; t < 64 * 8; t += 256) {
            int m = t >> 3, kk = t & 7;
            As[kk][m] = A[(size_t)(bm + m) * K + k0 + kk];
        }
#pragma unroll
        for (int t = tid; t < 8 * 64; t += 256) {
            int kk = t >> 6, n = t & 63;
            int col = bn + n;
            Bs[kk][n] = (col < Nn) ? B[(size_t)(k0 + kk) * Nn + col] : 0.f;
        }
        __syncthreads();
#pragma unroll
        for (int kk = 0; kk < 8; kk++) {
            float4 a4 = *reinterpret_cast<const float4*>(&As[kk][trow * 4]);
            float4 b4 = *reinterpret_cast<const float4*>(&Bs[kk][tcol * 4]);
            float av[4] = {a4.x, a4.y, a4.z, a4.w};
            float bv[4] = {b4.x, b4.y, b4.z, b4.w};
#pragma unroll
            for (int i = 0; i < 4; i++)
#pragma unroll
                for (int j = 0; j < 4; j++)
                    acc[i][j] += av[i] * bv[j];
        }
        __syncthreads();
    }

#pragma unroll
    for (int i = 0; i < 4; i++) {
        int row = bm + trow * 4 + i;
#pragma unroll
        for (int j = 0; j < 4; j++) {
            int col = bn + tcol * 4 + j;
            if (col < Nn) {
                float v = acc[i][j];
                if (bias) v += bias[col];
                C[(size_t)row * Nn + col] = v;
            }
        }
    }
}

// ---------------- role combine (message path): m = relu(sum_r c_r*(lin_r+bm_r))
__global__ void combine1_k(const float* __restrict__ x, const float* __restrict__ bm_l) {
    int n = blockIdx.x;
    int o = threadIdx.x;
    float c0 = 2.f * x[n * XDIM + 0];
    float c1 = x[n * XDIM + 1];
    float c2 = x[n * XDIM + 2];
    const float* lp = g_lin + (size_t)n * NB;
    float v = c0 * (lp[o]           + bm_l[o])
            + c1 * (lp[128 + o]     + bm_l[128 + o])
            + c2 * (lp[256 + o]     + bm_l[256 + o]);
    g_m[(size_t)n * DIN + o] = fmaxf(v, 0.f);
}

__global__ void zero_ssum_k() {
    int idx = blockIdx.x * blockDim.x + threadIdx.x;
    if (idx < NN * DIN) g_ssum[idx] = 0.f;
}

// ---------------- edge scatter: one warp per edge, scalar float atomics -------
__global__ void edge_scatter_k(const int* __restrict__ src,
                               const int* __restrict__ dst) {
    int gw = (blockIdx.x * blockDim.x + threadIdx.x) >> 5;
    int lane = threadIdx.x & 31;
    if (gw >= EE) return;
    int s = src[gw];
    int d = dst[gw];
    float4 v = *reinterpret_cast<const float4*>(g_m + (size_t)s * DIN + lane * 4);
    float* p = g_ssum + (size_t)d * DIN + lane * 4;
    atomicAdd(p + 0, v.x);
    atomicAdd(p + 1, v.y);
    atomicAdd(p + 2, v.z);
    atomicAdd(p + 3, v.w);
}

// ---------------- build cat = [feats | aggr] ----------------------------------
__global__ void build_cat_k() {
    int idx = blockIdx.x * blockDim.x + threadIdx.x;
    if (idx >= NN * 2 * DIN) return;
    int n = idx >> 8, j = idx & 255;
    float v;
    if (j < DIN) {
        v = g_feats[(size_t)n * DIN + j];
    } else {
        float c = g_cnt[n];
        v = (c > 0.f) ? g_ssum[(size_t)n * DIN + (j - DIN)] / c : 0.f;
    }
    g_cat[idx] = v;
}

// ---------------- role combine 2 + L2 normalize -> feats ----------------------
__global__ void combine2_norm_k(const float* __restrict__ x, const float* __restrict__ ba_l) {
    int n = blockIdx.x;
    int o = threadIdx.x;
    float c0 = 2.f * x[n * XDIM + 0];
    float c1 = x[n * XDIM + 1];
    float c2 = x[n * XDIM + 2];
    const float* lp = g_lin + (size_t)n * NB;
    float v = c0 * (lp[o]       + ba_l[o])
            + c1 * (lp[128 + o] + ba_l[128 + o])
            + c2 * (lp[256 + o] + ba_l[256 + o]);
    v = fmaxf(v, 0.f);

    __shared__ float red[4];
    float s = v * v;
#pragma unroll
    for (int off = 16; off; off >>= 1) s += __shfl_xor_sync(0xffffffffu, s, off);
    if ((threadIdx.x & 31) == 0) red[threadIdx.x >> 5] = s;
    __syncthreads();
    float tot = red[0] + red[1] + red[2] + red[3];
    float norm = fmaxf(sqrtf(tot), 1e-12f);
    g_feats[(size_t)n * DIN + o] = v / norm;
}

// ---------------- log_softmax over rows of 40 (one warp per node) -------------
__global__ void logsoftmax_k(float* __restrict__ out) {
    int n = (blockIdx.x * blockDim.x + threadIdx.x) >> 5;
    int lane = threadIdx.x & 31;
    if (n >= NN) return;
    const float* lp = g_logits + (size_t)n * DOUT;
    float v0 = lp[lane];
    float v1 = (lane < DOUT - 32) ? lp[32 + lane] : -INFINITY;
    float mx = fmaxf(v0, v1);
#pragma unroll
    for (int off = 16; off; off >>= 1) mx = fmaxf(mx, __shfl_xor_sync(0xffffffffu, mx, off));
    float se = expf(v0 - mx) + ((lane < DOUT - 32) ? expf(v1 - mx) : 0.f);
#pragma unroll
    for (int off = 16; off; off >>= 1) se += __shfl_xor_sync(0xffffffffu, se, off);
    float l = mx + logf(se);
    float* op = out + (size_t)n * DOUT;
    op[lane] = v0 - l;
    if (lane < DOUT - 32) op[32 + lane] = v1 - l;
}

// ---------------- host orchestration ------------------------------------------

static inline void run_gemm(const float* A, const float* B, float* C,
                            const float* bias, int M, int K, int Nn,
                            cudaStream_t st) {
    dim3 grid((Nn + 63) / 64, M / 64);
    sgemm_k<<<grid, 256, 0, st>>>(A, B, C, bias, M, K, Nn);
}

extern "C" void kernel_launch(void* const* d_in, const int* in_sizes, int n_in,
                              void* d_out, int out_size) {
    const float* x  = (const float*)d_in[0];
    const int*   ei = (const int*)d_in[1];     // int32! (JAX x64 disabled)
    const float* Wm = (const float*)d_in[2];
    const float* bm = (const float*)d_in[3];
    const float* Wa = (const float*)d_in[4];
    const float* ba = (const float*)d_in[5];
    const float* W1 = (const float*)d_in[6];
    const float* b1 = (const float*)d_in[7];
    const float* W2 = (const float*)d_in[8];
    const float* b2 = (const float*)d_in[9];
    float* out = (float*)d_out;

    cudaStream_t st = 0;

    float *p_feats, *p_lin, *p_cat, *p_z, *p_logits, *p_Bm, *p_Ba;
    cudaGetSymbolAddress((void**)&p_feats,  g_feats);
    cudaGetSymbolAddress((void**)&p_lin,    g_lin);
    cudaGetSymbolAddress((void**)&p_cat,    g_cat);
    cudaGetSymbolAddress((void**)&p_z,      g_z);
    cudaGetSymbolAddress((void**)&p_logits, g_logits);
    cudaGetSymbolAddress((void**)&p_Bm,     g_Bm);
    cudaGetSymbolAddress((void**)&p_Ba,     g_Ba);

    const int* src = ei;        // edge_index[0], E int32
    const int* dst = ei + EE;   // edge_index[1]

    init_feats_k<<<(NN * DIN + 255) / 256, 256, 0, st>>>(x);
    zero_cnt_k<<<(NN + 255) / 256, 256, 0, st>>>();
    count_deg_k<<<(EE + 255) / 256, 256, 0, st>>>(dst);

    for (int l = 0; l < 2; l++) {
        const float* Wm_l = Wm + (size_t)l * RR * DIN * DIN;
        const float* bm_l = bm + (size_t)l * RR * DIN;
        const float* Wa_l = Wa + (size_t)l * RR * 2 * DIN * DIN;
        const float* ba_l = ba + (size_t)l * RR * DIN;

        // lin = feats @ Bm  -> (N, 384)
        pack_Bm_k<<<(3 * DIN * DIN + 255) / 256, 256, 0, st>>>(Wm_l);
        run_gemm(p_feats, p_Bm, p_lin, nullptr, NN, DIN, NB, st);
        combine1_k<<<NN, DIN, 0, st>>>(x, bm_l);

        // aggregate over edges
        zero_ssum_k<<<(NN * DIN + 255) / 256, 256, 0, st>>>();
        edge_scatter_k<<<(EE * 32 + 255) / 256, 256, 0, st>>>(src, dst);
        build_cat_k<<<(NN * 2 * DIN + 255) / 256, 256, 0, st>>>();

        // lin2 = cat @ Ba -> (N, 384); combine + normalize -> feats
        pack_Ba_k<<<(3 * 2 * DIN * DIN + 255) / 256, 256, 0, st>>>(Wa_l);
        run_gemm(p_cat, p_Ba, p_lin, nullptr, NN, 2 * DIN, NB, st);
        combine2_norm_k<<<NN, DIN, 0, st>>>(x, ba_l);
    }

    // head: z = feats@W1 + b1 ; logits = z@W2 + b2 ; log_softmax
    run_gemm(p_feats, W1, p_z, b1, NN, DIN, DIN, st);
    run_gemm(p_z, W2, p_logits, b2, NN, DIN, DOUT, st);
    logsoftmax_k<<<(NN * 32 + 255) / 256, 256, 0, st>>>(out);
}

// round 7
// speedup vs baseline: 1.2670x; 1.2670x over previous
#include <cuda_runtime.h>
#include <cuda_bf16.h>
#include <math.h>

#define NN    40000
#define MPAD  40064    // 313 * 128
#define RR    4
#define DIN   128
#define DOUT  40
#define EE    480000
#define XDIM  132      // R + DIN
#define NB    384      // 3 effective roles * 128

// ---------------- scratch (device globals; no allocation allowed) -------------
__device__ __align__(256) float g_feats[MPAD * DIN];
__device__ __align__(256) float g_lin[MPAD * NB];
__device__ __align__(256) float g_m[NN * DIN];
__device__ __align__(256) float g_ssum[MPAD * DIN];
__device__ __align__(256) float g_cnt[NN];
__device__ __align__(256) float g_z[MPAD * DIN];
__device__ __align__(256) float g_logits[MPAD * DOUT];
__device__ __align__(256) float g_Bm[DIN * NB];        // packed Wm[l] -> (128,384)
__device__ __align__(256) float g_Ba[2 * DIN * NB];    // packed Wa[l] -> (256,384)

// ---------------- small helper kernels ----------------------------------------

__global__ void init_feats_k(const float* __restrict__ x) {
    int idx = blockIdx.x * blockDim.x + threadIdx.x;
    if (idx >= NN * DIN) return;
    int n = idx >> 7, i = idx & 127;
    g_feats[idx] = x[n * XDIM + RR + i];
}

__global__ void zero_cnt_k() {
    int idx = blockIdx.x * blockDim.x + threadIdx.x;
    if (idx < NN) g_cnt[idx] = 0.f;
}

__global__ void count_deg_k(const int* __restrict__ dst) {
    int e = blockIdx.x * blockDim.x + threadIdx.x;
    if (e >= EE) return;
    atomicAdd(&g_cnt[dst[e]], 1.0f);
}

// pack Wm[l] (R,128,128) -> B (128, 384), B[k][r*128+o] = Wm[r][k][o], r<3
__global__ void pack_Bm_k(const float* __restrict__ Wm_l) {
    int idx = blockIdx.x * blockDim.x + threadIdx.x;
    if (idx >= 3 * DIN * DIN) return;
    int r = idx / (DIN * DIN);
    int rem = idx - r * DIN * DIN;
    int k = rem >> 7, o = rem & 127;
    g_Bm[k * NB + r * DIN + o] = Wm_l[r * DIN * DIN + k * DIN + o];
}

// pack Wa[l] (R,256,128) -> B (256, 384)
__global__ void pack_Ba_k(const float* __restrict__ Wa_l) {
    int idx = blockIdx.x * blockDim.x + threadIdx.x;
    if (idx >= 3 * 2 * DIN * DIN) return;
    int r = idx / (2 * DIN * DIN);
    int rem = idx - r * 2 * DIN * DIN;
    int k = rem >> 7, o = rem & 127;
    g_Ba[k * NB + r * DIN + o] = Wa_l[r * 2 * DIN * DIN + k * DIN + o];
}

// ---------------- SGEMM: C(M,Nn) = A(M,K) @ B(K,Nn) (+bias) (+=C) -------------
// BM=BN=128, BK=8, 256 threads, 8x8 register tile, double-buffered smem.
// M must be a multiple of 128 (padded). Nn multiple of 4. K multiple of 8.
#define BM 128
#define BN 128
#define BK 8
__global__ void __launch_bounds__(256) sgemm2_k(
    const float* __restrict__ A, const float* __restrict__ B,
    float* __restrict__ C, const float* __restrict__ bias,
    int K, int Nn, int accumulate)
{
    __shared__ float As[2][BK][BM];
    __shared__ float Bs[2][BK][BN];
    const int tid = threadIdx.x;
    const int bm = blockIdx.y * BM;
    const int bn = blockIdx.x * BN;

    // A tile load map: 128 rows x 8 cols = 256 float4; thread -> (row, col4)
    const int arow = tid >> 1;
    const int acol = (tid & 1) * 4;
    // B tile load map: 8 rows x 128 cols = 256 float4
    const int brow = tid >> 5;
    const int bcol = (tid & 31) * 4;

    const int trow = (tid >> 4) * 8;
    const int tcol = (tid & 15) * 8;

    float acc[8][8];
#pragma unroll
    for (int i = 0; i < 8; i++)
#pragma unroll
        for (int j = 0; j < 8; j++) acc[i][j] = 0.f;

    const int nk = K / BK;

    // prologue: tile 0 -> buf 0
    {
        float4 a4 = *reinterpret_cast<const float4*>(&A[(size_t)(bm + arow) * K + acol]);
        As[0][acol + 0][arow] = a4.x;
        As[0][acol + 1][arow] = a4.y;
        As[0][acol + 2][arow] = a4.z;
        As[0][acol + 3][arow] = a4.w;
        float4 b4 = make_float4(0.f, 0.f, 0.f, 0.f);
        if (bn + bcol < Nn)
            b4 = *reinterpret_cast<const float4*>(&B[(size_t)brow * Nn + bn + bcol]);
        *reinterpret_cast<float4*>(&Bs[0][brow][bcol]) = b4;
    }
    __syncthreads();

    int buf = 0;
    for (int t = 0; t < nk; t++) {
        float4 a4n, b4n;
        if (t + 1 < nk) {
            int k0 = (t + 1) * BK;
            a4n = *reinterpret_cast<const float4*>(&A[(size_t)(bm + arow) * K + k0 + acol]);
            b4n = make_float4(0.f, 0.f, 0.f, 0.f);
            if (bn + bcol < Nn)
                b4n = *reinterpret_cast<const float4*>(&B[(size_t)(k0 + brow) * Nn + bn + bcol]);
        }
#pragma unroll
        for (int kk = 0; kk < BK; kk++) {
            float4 a0 = *reinterpret_cast<const float4*>(&As[buf][kk][trow]);
            float4 a1 = *reinterpret_cast<const float4*>(&As[buf][kk][trow + 4]);
            float4 b0 = *reinterpret_cast<const float4*>(&Bs[buf][kk][tcol]);
            float4 b1 = *reinterpret_cast<const float4*>(&Bs[buf][kk][tcol + 4]);
            float af[8] = {a0.x, a0.y, a0.z, a0.w, a1.x, a1.y, a1.z, a1.w};
            float bf[8] = {b0.x, b0.y, b0.z, b0.w, b1.x, b1.y, b1.z, b1.w};
#pragma unroll
            for (int i = 0; i < 8; i++)
#pragma unroll
                for (int j = 0; j < 8; j++)
                    acc[i][j] += af[i] * bf[j];
        }
        if (t + 1 < nk) {
            int nb = buf ^ 1;
            As[nb][acol + 0][arow] = a4n.x;
            As[nb][acol + 1][arow] = a4n.y;
            As[nb][acol + 2][arow] = a4n.z;
            As[nb][acol + 3][arow] = a4n.w;
            *reinterpret_cast<float4*>(&Bs[nb][brow][bcol]) = b4n;
            __syncthreads();
            buf = nb;
        }
    }

#pragma unroll
    for (int i = 0; i < 8; i++) {
        size_t row = (size_t)(bm + trow + i);
#pragma unroll
        for (int j = 0; j < 8; j += 4) {
            int col = bn + tcol + j;
            if (col < Nn) {
                float4 v = make_float4(acc[i][j], acc[i][j + 1], acc[i][j + 2], acc[i][j + 3]);
                if (bias) {
                    v.x += bias[col]; v.y += bias[col + 1];
                    v.z += bias[col + 2]; v.w += bias[col + 3];
                }
                float4* cp = reinterpret_cast<float4*>(&C[row * Nn + col]);
                if (accumulate) {
                    float4 o = *cp;
                    v.x += o.x; v.y += o.y; v.z += o.z; v.w += o.w;
                }
                *cp = v;
            }
        }
    }
}

// ---------------- role combine (message path): m = relu(sum_r c_r*(lin_r+bm_r))
__global__ void combine1_k(const float* __restrict__ x, const float* __restrict__ bm_l) {
    int n = blockIdx.x;
    int o = threadIdx.x;
    float c0 = 2.f * x[n * XDIM + 0];
    float c1 = x[n * XDIM + 1];
    float c2 = x[n * XDIM + 2];
    const float* lp = g_lin + (size_t)n * NB;
    float v = c0 * (lp[o]       + bm_l[o])
            + c1 * (lp[128 + o] + bm_l[128 + o])
            + c2 * (lp[256 + o] + bm_l[256 + o]);
    g_m[(size_t)n * DIN + o] = fmaxf(v, 0.f);
}

__global__ void zero_ssum_k() {
    int idx = blockIdx.x * blockDim.x + threadIdx.x;
    if (idx < MPAD * DIN) g_ssum[idx] = 0.f;
}

// ---------------- edge scatter: one warp per edge, float4 vector atomics ------
__global__ void edge_scatter_k(const int* __restrict__ src,
                               const int* __restrict__ dst) {
    int gw = (blockIdx.x * blockDim.x + threadIdx.x) >> 5;
    int lane = threadIdx.x & 31;
    if (gw >= EE) return;
    int s = src[gw];
    int d = dst[gw];
    float4 v = *reinterpret_cast<const float4*>(g_m + (size_t)s * DIN + lane * 4);
    float4* p = reinterpret_cast<float4*>(g_ssum + (size_t)d * DIN + lane * 4);
    atomicAdd(p, v);
}

// ---------------- aggr = ssum / max(cnt,1) (0 where cnt==0), in place ---------
__global__ void avg_k() {
    int idx = blockIdx.x * blockDim.x + threadIdx.x;
    if (idx >= NN * DIN) return;
    int n = idx >> 7;
    float c = g_cnt[n];
    g_ssum[idx] = (c > 0.f) ? g_ssum[idx] / c : 0.f;
}

// ---------------- role combine 2 + L2 normalize -> feats ----------------------
__global__ void combine2_norm_k(const float* __restrict__ x, const float* __restrict__ ba_l) {
    int n = blockIdx.x;
    int o = threadIdx.x;
    float c0 = 2.f * x[n * XDIM + 0];
    float c1 = x[n * XDIM + 1];
    float c2 = x[n * XDIM + 2];
    const float* lp = g_lin + (size_t)n * NB;
    float v = c0 * (lp[o]       + ba_l[o])
            + c1 * (lp[128 + o] + ba_l[128 + o])
            + c2 * (lp[256 + o] + ba_l[256 + o]);
    v = fmaxf(v, 0.f);

    __shared__ float red[4];
    float s = v * v;
#pragma unroll
    for (int off = 16; off; off >>= 1) s += __shfl_xor_sync(0xffffffffu, s, off);
    if ((threadIdx.x & 31) == 0) red[threadIdx.x >> 5] = s;
    __syncthreads();
    float tot = red[0] + red[1] + red[2] + red[3];
    float norm = fmaxf(sqrtf(tot), 1e-12f);
    g_feats[(size_t)n * DIN + o] = v / norm;
}

// ---------------- log_softmax over rows of 40 (one warp per node) -------------
__global__ void logsoftmax_k(float* __restrict__ out) {
    int n = (blockIdx.x * blockDim.x + threadIdx.x) >> 5;
    int lane = threadIdx.x & 31;
    if (n >= NN) return;
    const float* lp = g_logits + (size_t)n * DOUT;
    float v0 = lp[lane];
    float v1 = (lane < DOUT - 32) ? lp[32 + lane] : -INFINITY;
    float mx = fmaxf(v0, v1);
#pragma unroll
    for (int off = 16; off; off >>= 1) mx = fmaxf(mx, __shfl_xor_sync(0xffffffffu, mx, off));
    float se = expf(v0 - mx) + ((lane < DOUT - 32) ? expf(v1 - mx) : 0.f);
#pragma unroll
    for (int off = 16; off; off >>= 1) se += __shfl_xor_sync(0xffffffffu, se, off);
    float l = mx + logf(se);
    float* op = out + (size_t)n * DOUT;
    op[lane] = v0 - l;
    if (lane < DOUT - 32) op[32 + lane] = v1 - l;
}

// ---------------- host orchestration ------------------------------------------

static inline void run_gemm(const float* A, const float* B, float* C,
                            const float* bias, int K, int Nn, int accumulate,
                            cudaStream_t st) {
    dim3 grid((Nn + BN - 1) / BN, MPAD / BM);
    sgemm2_k<<<grid, 256, 0, st>>>(A, B, C, bias, K, Nn, accumulate);
}

extern "C" void kernel_launch(void* const* d_in, const int* in_sizes, int n_in,
                              void* d_out, int out_size) {
    const float* x  = (const float*)d_in[0];
    const int*   ei = (const int*)d_in[1];     // int32 (JAX x64 disabled)
    const float* Wm = (const float*)d_in[2];
    const float* bm = (const float*)d_in[3];
    const float* Wa = (const float*)d_in[4];
    const float* ba = (const float*)d_in[5];
    const float* W1 = (const float*)d_in[6];
    const float* b1 = (const float*)d_in[7];
    const float* W2 = (const float*)d_in[8];
    const float* b2 = (const float*)d_in[9];
    float* out = (float*)d_out;

    cudaStream_t st = 0;

    float *p_feats, *p_lin, *p_ssum, *p_z, *p_logits, *p_Bm, *p_Ba;
    cudaGetSymbolAddress((void**)&p_feats,  g_feats);
    cudaGetSymbolAddress((void**)&p_lin,    g_lin);
    cudaGetSymbolAddress((void**)&p_ssum,   g_ssum);
    cudaGetSymbolAddress((void**)&p_z,      g_z);
    cudaGetSymbolAddress((void**)&p_logits, g_logits);
    cudaGetSymbolAddress((void**)&p_Bm,     g_Bm);
    cudaGetSymbolAddress((void**)&p_Ba,     g_Ba);

    const int* src = ei;        // edge_index[0], E int32
    const int* dst = ei + EE;   // edge_index[1]

    for (int l = 0; l < 2; l++) {
        const float* Wm_l = Wm + (size_t)l * RR * DIN * DIN;
        const float* bm_l = bm + (size_t)l * RR * DIN;
        const float* Wa_l = Wa + (size_t)l * RR * 2 * DIN * DIN;
        const float* ba_l = ba + (size_t)l * RR * DIN;

        if (l == 0) {
            // ordered so the 4th launch (ncu capture slot) is the big GEMM
            init_feats_k<<<(NN * DIN + 255) / 256, 256, 0, st>>>(x);
            pack_Bm_k<<<(3 * DIN * DIN + 255) / 256, 256, 0, st>>>(Wm_l);
            zero_cnt_k<<<(NN + 255) / 256, 256, 0, st>>>();
            run_gemm(p_feats, p_Bm, p_lin, nullptr, DIN, NB, 0, st);
            count_deg_k<<<(EE + 255) / 256, 256, 0, st>>>(dst);
        } else {
            pack_Bm_k<<<(3 * DIN * DIN + 255) / 256, 256, 0, st>>>(Wm_l);
            run_gemm(p_feats, p_Bm, p_lin, nullptr, DIN, NB, 0, st);
        }
        combine1_k<<<NN, DIN, 0, st>>>(x, bm_l);

        // aggregate over edges -> g_ssum (then averaged in place)
        zero_ssum_k<<<(MPAD * DIN + 255) / 256, 256, 0, st>>>();
        edge_scatter_k<<<(EE * 32 + 255) / 256, 256, 0, st>>>(src, dst);
        avg_k<<<(NN * DIN + 255) / 256, 256, 0, st>>>();

        // lin2 = feats @ Ba[0:128] + aggr @ Ba[128:256]   (no cat materialized)
        pack_Ba_k<<<(3 * 2 * DIN * DIN + 255) / 256, 256, 0, st>>>(Wa_l);
        run_gemm(p_feats, p_Ba,            p_lin, nullptr, DIN, NB, 0, st);
        run_gemm(p_ssum,  p_Ba + DIN * NB, p_lin, nullptr, DIN, NB, 1, st);
        combine2_norm_k<<<NN, DIN, 0, st>>>(x, ba_l);
    }

    // head: z = feats@W1 + b1 ; logits = z@W2 + b2 ; log_softmax
    run_gemm(p_feats, W1, p_z, b1, DIN, DIN, 0, st);
    run_gemm(p_z, W2, p_logits, b2, DIN, DOUT, 0, st);
    logsoftmax_k<<<(NN * 32 + 255) / 256, 256, 0, st>>>(out);
}

// round 12
// speedup vs baseline: 1.6224x; 1.2805x over previous
#include <cuda_runtime.h>
#include <cuda_bf16.h>
#include <math.h>
#include <stdint.h>

#define NN    40000
#define MPAD  40064    // 313 * 128
#define RR    4
#define DIN   128
#define DOUT  40
#define EE    480000
#define XDIM  132      // R + DIN
#define NB    384      // 3 effective roles * 128

#define SA_STR 136     // bf16 elems per A row in smem (128 + 8 pad)
#define SB_STR 136     // bf16 elems per Bt row in smem
#define SMEM_BYTES ((2 * 128 * SA_STR + 2 * 128 * SB_STR) * 2)   // 139264

// ---------------- scratch (device globals; no allocation allowed) -------------
__device__ __align__(256) float g_feats[MPAD * DIN];
__device__ __align__(256) float g_lin[MPAD * NB];
__device__ __align__(256) float g_m[NN * DIN];
__device__ __align__(256) float g_ssum[MPAD * DIN];
__device__ __align__(256) float g_cnt[NN];
__device__ __align__(256) float g_z[MPAD * DIN];
__device__ __align__(256) float g_logits[MPAD * DOUT];

// ---------------- warp-mma helpers (baseline PTX, no 'a' features) ------------
__device__ __forceinline__ uint32_t smem_u32(const void* p) {
    uint32_t a;
    asm("{ .reg .u64 t; cvta.to.shared.u64 t, %1; cvt.u32.u64 %0, t; }" : "=r"(a) : "l"(p));
    return a;
}
__device__ __forceinline__ void ldmatrix_x4(uint32_t* r, uint32_t addr) {
    asm volatile("ldmatrix.sync.aligned.m8n8.x4.shared.b16 {%0,%1,%2,%3}, [%4];"
        : "=r"(r[0]), "=r"(r[1]), "=r"(r[2]), "=r"(r[3]) : "r"(addr));
}
__device__ __forceinline__ void mma_bf16(float* d, const uint32_t* a, uint32_t b0, uint32_t b1) {
    asm volatile("mma.sync.aligned.m16n8k16.row.col.f32.bf16.bf16.f32 "
        "{%0,%1,%2,%3}, {%4,%5,%6,%7}, {%8,%9}, {%0,%1,%2,%3};"
        : "+f"(d[0]), "+f"(d[1]), "+f"(d[2]), "+f"(d[3])
        : "r"(a[0]), "r"(a[1]), "r"(a[2]), "r"(a[3]), "r"(b0), "r"(b1));
}

// ================= tensor-core GEMM via mma.sync ==============================
// C(MPAD,Nn) = A(MPAD,128) @ B(128,Nn) (+bias) (+=C), fp32 in/out.
// bf16 hi/lo split, 3 accumulating passes: Ah*Bh + Al*Bh + Ah*Bl.
// CTA tile 128x128, K=128 resident in smem. Nn must be a multiple of 128.
// blayout 0: B[k*Nn+col].  blayout 1 (role-packed): W[r][k0w+k][o], r=col>>7, o=col&127.
__global__ void __launch_bounds__(256) mmagemm_k(
    const float* __restrict__ A, const float* __restrict__ Braw,
    float* __restrict__ C, const float* __restrict__ bias,
    int Nn, int accumulate, int blayout, int k0w, int ktot)
{
    extern __shared__ __nv_bfloat16 sm[];
    __nv_bfloat16* sAh = sm;
    __nv_bfloat16* sAl = sm + 128 * SA_STR;
    __nv_bfloat16* sBh = sm + 2 * 128 * SA_STR;
    __nv_bfloat16* sBl = sm + 2 * 128 * SA_STR + 128 * SB_STR;

    const int tid = threadIdx.x;
    const int bm = blockIdx.y * 128;
    const int bn = blockIdx.x * 128;

    // ---- A tile (128x128 fp32) -> sAh/sAl --------------------------------
#pragma unroll
    for (int i = 0; i < 16; i++) {
        int lin = tid + i * 256;          // 0..4095 float4 slots
        int row = lin >> 5;
        int k4  = (lin & 31) << 2;
        float4 v = *reinterpret_cast<const float4*>(&A[(size_t)(bm + row) * 128 + k4]);
        float f[4] = {v.x, v.y, v.z, v.w};
        int off = row * SA_STR + k4;
#pragma unroll
        for (int j = 0; j < 4; j++) {
            __nv_bfloat16 h = __float2bfloat16(f[j]);
            sAh[off + j] = h;
            sAl[off + j] = __float2bfloat16(f[j] - __bfloat162float(h));
        }
    }

    // ---- B tile -> sBh/sBl transposed: sBt[n][k] -------------------------
    for (int i = 0; i < 64; i++) {
        int lin = tid + i * 256;          // 0..16383
        int k = lin >> 7;
        int n = lin & 127;                // lanes consecutive in n -> coalesced read
        int col = bn + n;
        float v = (blayout == 0)
            ? Braw[(size_t)k * Nn + col]
            : Braw[((size_t)(col >> 7) * ktot + (k0w + k)) * 128 + (col & 127)];
        __nv_bfloat16 h = __float2bfloat16(v);
        sBh[n * SB_STR + k] = h;
        sBl[n * SB_STR + k] = __float2bfloat16(v - __bfloat162float(h));
    }
    __syncthreads();

    // ---- warp tiles: 8 warps as 4(M) x 2(N), each 32(M) x 64(N) ----------
    const int w = tid >> 5, lane = tid & 31;
    const int wm = (w & 3) * 32;
    const int wn = (w >> 2) * 64;
    const int mi = lane >> 3, r8 = lane & 7;

    // ldmatrix lane offsets (bytes)
    uint32_t aoff0  = (uint32_t)(((wm + ((mi & 1) << 3) + r8) * SA_STR + ((mi >> 1) << 3)) * 2);
    uint32_t aoff16 = aoff0 + 16 * SA_STR * 2;
    uint32_t boffb  = (uint32_t)(((wn + ((mi >> 1) << 3) + r8) * SB_STR + ((mi & 1) << 3)) * 2);

    uint32_t sAh32 = smem_u32(sAh), sAl32 = smem_u32(sAl);
    uint32_t sBh32 = smem_u32(sBh), sBl32 = smem_u32(sBl);

    float acc[2][8][4];
#pragma unroll
    for (int a = 0; a < 2; a++)
#pragma unroll
        for (int b = 0; b < 8; b++)
#pragma unroll
            for (int c = 0; c < 4; c++) acc[a][b][c] = 0.f;

#pragma unroll
    for (int pass = 0; pass < 3; pass++) {
        uint32_t ab = (pass == 1) ? sAl32 : sAh32;
        uint32_t bb = (pass == 2) ? sBl32 : sBh32;
#pragma unroll
        for (int k0 = 0; k0 < 128; k0 += 16) {
            uint32_t A0[4], A1[4], B[4][4];
            ldmatrix_x4(A0, ab + aoff0 + k0 * 2);
            ldmatrix_x4(A1, ab + aoff16 + k0 * 2);
#pragma unroll
            for (int q = 0; q < 4; q++)
                ldmatrix_x4(B[q], bb + boffb + (uint32_t)(q * 16 * SB_STR * 2) + k0 * 2);
#pragma unroll
            for (int m2 = 0; m2 < 2; m2++) {
                uint32_t* Af = m2 ? A1 : A0;
#pragma unroll
                for (int nf = 0; nf < 8; nf++) {
                    uint32_t b0 = B[nf >> 1][(nf & 1) ? 2 : 0];
                    uint32_t b1 = B[nf >> 1][(nf & 1) ? 3 : 1];
                    mma_bf16(acc[m2][nf], Af, b0, b1);
                }
            }
        }
    }

    // ---- epilogue --------------------------------------------------------
    const int g = lane >> 2, t4 = lane & 3;
#pragma unroll
    for (int m2 = 0; m2 < 2; m2++) {
#pragma unroll
        for (int nf = 0; nf < 8; nf++) {
            int row = bm + wm + m2 * 16 + g;
            int col = bn + wn + nf * 8 + t4 * 2;
            float* c0 = &C[(size_t)row * Nn + col];
            float* c1 = &C[(size_t)(row + 8) * Nn + col];
            float2 v0 = make_float2(acc[m2][nf][0], acc[m2][nf][1]);
            float2 v1 = make_float2(acc[m2][nf][2], acc[m2][nf][3]);
            if (bias) {
                float bb0 = bias[col], bb1 = bias[col + 1];
                v0.x += bb0; v0.y += bb1; v1.x += bb0; v1.y += bb1;
            }
            if (accumulate) {
                float2 o0 = *reinterpret_cast<float2*>(c0);
                float2 o1 = *reinterpret_cast<float2*>(c1);
                v0.x += o0.x; v0.y += o0.y; v1.x += o1.x; v1.y += o1.y;
            }
            *reinterpret_cast<float2*>(c0) = v0;
            *reinterpret_cast<float2*>(c1) = v1;
        }
    }
}

// ---------------- SIMT SGEMM (kept for W2, N=40) ------------------------------
#define BM 128
#define BN 128
#define BK 8
__global__ void __launch_bounds__(256) sgemm2_k(
    const float* __restrict__ A, const float* __restrict__ B,
    float* __restrict__ C, const float* __restrict__ bias,
    int K, int Nn, int accumulate)
{
    __shared__ float As[2][BK][BM];
    __shared__ float Bs[2][BK][BN];
    const int tid = threadIdx.x;
    const int bm = blockIdx.y * BM;
    const int bn = blockIdx.x * BN;
    const int arow = tid >> 1;
    const int acol = (tid & 1) * 4;
    const int brow = tid >> 5;
    const int bcol = (tid & 31) * 4;
    const int trow = (tid >> 4) * 8;
    const int tcol = (tid & 15) * 8;

    float acc[8][8];
#pragma unroll
    for (int i = 0; i < 8; i++)
#pragma unroll
        for (int j = 0; j < 8; j++) acc[i][j] = 0.f;

    const int nk = K / BK;
    {
        float4 a4 = *reinterpret_cast<const float4*>(&A[(size_t)(bm + arow) * K + acol]);
        As[0][acol + 0][arow] = a4.x; As[0][acol + 1][arow] = a4.y;
        As[0][acol + 2][arow] = a4.z; As[0][acol + 3][arow] = a4.w;
        float4 b4 = make_float4(0.f, 0.f, 0.f, 0.f);
        if (bn + bcol < Nn)
            b4 = *reinterpret_cast<const float4*>(&B[(size_t)brow * Nn + bn + bcol]);
        *reinterpret_cast<float4*>(&Bs[0][brow][bcol]) = b4;
    }
    __syncthreads();

    int buf = 0;
    for (int t = 0; t < nk; t++) {
        float4 a4n, b4n;
        if (t + 1 < nk) {
            int kk0 = (t + 1) * BK;
            a4n = *reinterpret_cast<const float4*>(&A[(size_t)(bm + arow) * K + kk0 + acol]);
            b4n = make_float4(0.f, 0.f, 0.f, 0.f);
            if (bn + bcol < Nn)
                b4n = *reinterpret_cast<const float4*>(&B[(size_t)(kk0 + brow) * Nn + bn + bcol]);
        }
#pragma unroll
        for (int kk = 0; kk < BK; kk++) {
            float4 a0 = *reinterpret_cast<const float4*>(&As[buf][kk][trow]);
            float4 a1 = *reinterpret_cast<const float4*>(&As[buf][kk][trow + 4]);
            float4 b0 = *reinterpret_cast<const float4*>(&Bs[buf][kk][tcol]);
            float4 b1 = *reinterpret_cast<const float4*>(&Bs[buf][kk][tcol + 4]);
            float af[8] = {a0.x, a0.y, a0.z, a0.w, a1.x, a1.y, a1.z, a1.w};
            float bf[8] = {b0.x, b0.y, b0.z, b0.w, b1.x, b1.y, b1.z, b1.w};
#pragma unroll
            for (int i = 0; i < 8; i++)
#pragma unroll
                for (int j = 0; j < 8; j++)
                    acc[i][j] += af[i] * bf[j];
        }
        if (t + 1 < nk) {
            int nb = buf ^ 1;
            As[nb][acol + 0][arow] = a4n.x; As[nb][acol + 1][arow] = a4n.y;
            As[nb][acol + 2][arow] = a4n.z; As[nb][acol + 3][arow] = a4n.w;
            *reinterpret_cast<float4*>(&Bs[nb][brow][bcol]) = b4n;
            __syncthreads();
            buf = nb;
        }
    }
#pragma unroll
    for (int i = 0; i < 8; i++) {
        size_t row = (size_t)(bm + trow + i);
#pragma unroll
        for (int j = 0; j < 8; j += 4) {
            int col = bn + tcol + j;
            if (col < Nn) {
                float4 v = make_float4(acc[i][j], acc[i][j + 1], acc[i][j + 2], acc[i][j + 3]);
                if (bias) {
                    v.x += bias[col]; v.y += bias[col + 1];
                    v.z += bias[col + 2]; v.w += bias[col + 3];
                }
                float4* cp = reinterpret_cast<float4*>(&C[row * Nn + col]);
                if (accumulate) {
                    float4 o = *cp;
                    v.x += o.x; v.y += o.y; v.z += o.z; v.w += o.w;
                }
                *cp = v;
            }
        }
    }
}

// ---------------- small/elementwise kernels -----------------------------------
__global__ void init_feats_k(const float* __restrict__ x) {
    int idx = blockIdx.x * blockDim.x + threadIdx.x;
    if (idx >= NN * DIN) return;
    int n = idx >> 7, i = idx & 127;
    g_feats[idx] = x[n * XDIM + RR + i];
}
__global__ void zero_cnt_k() {
    int idx = blockIdx.x * blockDim.x + threadIdx.x;
    if (idx < NN) g_cnt[idx] = 0.f;
}
__global__ void count_deg_k(const int* __restrict__ dst) {
    int e = blockIdx.x * blockDim.x + threadIdx.x;
    if (e >= EE) return;
    atomicAdd(&g_cnt[dst[e]], 1.0f);
}
__global__ void combine1_k(const float* __restrict__ x, const float* __restrict__ bm_l) {
    int n = blockIdx.x;
    int o = threadIdx.x;
    float c0 = 2.f * x[n * XDIM + 0];
    float c1 = x[n * XDIM + 1];
    float c2 = x[n * XDIM + 2];
    const float* lp = g_lin + (size_t)n * NB;
    float v = c0 * (lp[o]       + bm_l[o])
            + c1 * (lp[128 + o] + bm_l[128 + o])
            + c2 * (lp[256 + o] + bm_l[256 + o]);
    g_m[(size_t)n * DIN + o] = fmaxf(v, 0.f);
}
__global__ void zero_ssum_k() {
    int idx = blockIdx.x * blockDim.x + threadIdx.x;
    if (idx < NN * DIN) g_ssum[idx] = 0.f;
}
__global__ void edge_scatter_k(const int* __restrict__ src,
                               const int* __restrict__ dst) {
    int gw = (blockIdx.x * blockDim.x + threadIdx.x) >> 5;
    int lane = threadIdx.x & 31;
    if (gw >= EE) return;
    int s = src[gw];
    int d = dst[gw];
    float4 v = *reinterpret_cast<const float4*>(g_m + (size_t)s * DIN + lane * 4);
    float4* p = reinterpret_cast<float4*>(g_ssum + (size_t)d * DIN + lane * 4);
    atomicAdd(p, v);
}
__global__ void avg_k() {
    int idx = blockIdx.x * blockDim.x + threadIdx.x;
    if (idx >= NN * DIN) return;
    int n = idx >> 7;
    float c = g_cnt[n];
    g_ssum[idx] = (c > 0.f) ? g_ssum[idx] / c : 0.f;
}
__global__ void combine2_norm_k(const float* __restrict__ x, const float* __restrict__ ba_l) {
    int n = blockIdx.x;
    int o = threadIdx.x;
    float c0 = 2.f * x[n * XDIM + 0];
    float c1 = x[n * XDIM + 1];
    float c2 = x[n * XDIM + 2];
    const float* lp = g_lin + (size_t)n * NB;
    float v = c0 * (lp[o]       + ba_l[o])
            + c1 * (lp[128 + o] + ba_l[128 + o])
            + c2 * (lp[256 + o] + ba_l[256 + o]);
    v = fmaxf(v, 0.f);
    __shared__ float red[4];
    float s = v * v;
#pragma unroll
    for (int off = 16; off; off >>= 1) s += __shfl_xor_sync(0xffffffffu, s, off);
    if ((threadIdx.x & 31) == 0) red[threadIdx.x >> 5] = s;
    __syncthreads();
    float tot = red[0] + red[1] + red[2] + red[3];
    float norm = fmaxf(sqrtf(tot), 1e-12f);
    g_feats[(size_t)n * DIN + o] = v / norm;
}
__global__ void logsoftmax_k(float* __restrict__ out) {
    int n = (blockIdx.x * blockDim.x + threadIdx.x) >> 5;
    int lane = threadIdx.x & 31;
    if (n >= NN) return;
    const float* lp = g_logits + (size_t)n * DOUT;
    float v0 = lp[lane];
    float v1 = (lane < DOUT - 32) ? lp[32 + lane] : -INFINITY;
    float mx = fmaxf(v0, v1);
#pragma unroll
    for (int off = 16; off; off >>= 1) mx = fmaxf(mx, __shfl_xor_sync(0xffffffffu, mx, off));
    float se = expf(v0 - mx) + ((lane < DOUT - 32) ? expf(v1 - mx) : 0.f);
#pragma unroll
    for (int off = 16; off; off >>= 1) se += __shfl_xor_sync(0xffffffffu, se, off);
    float l = mx + logf(se);
    float* op = out + (size_t)n * DOUT;
    op[lane] = v0 - l;
    if (lane < DOUT - 32) op[32 + lane] = v1 - l;
}

// ---------------- host orchestration ------------------------------------------
static inline void run_mma(const float* A, const float* Braw, float* C,
                           const float* bias, int Nn, int accumulate,
                           int blayout, int k0, int ktot, cudaStream_t st) {
    dim3 grid(Nn / 128, MPAD / 128);
    mmagemm_k<<<grid, 256, SMEM_BYTES, st>>>(A, Braw, C, bias, Nn, accumulate, blayout, k0, ktot);
}

extern "C" void kernel_launch(void* const* d_in, const int* in_sizes, int n_in,
                              void* d_out, int out_size) {
    const float* x  = (const float*)d_in[0];
    const int*   ei = (const int*)d_in[1];     // int32 (JAX x64 disabled)
    const float* Wm = (const float*)d_in[2];
    const float* bm = (const float*)d_in[3];
    const float* Wa = (const float*)d_in[4];
    const float* ba = (const float*)d_in[5];
    const float* W1 = (const float*)d_in[6];
    const float* b1 = (const float*)d_in[7];
    const float* W2 = (const float*)d_in[8];
    const float* b2 = (const float*)d_in[9];
    float* out = (float*)d_out;

    cudaStream_t st = 0;

    // idempotent, host-side, not a stream op (safe under graph capture; no
    // static guard per harness rules)
    cudaFuncSetAttribute(mmagemm_k, cudaFuncAttributeMaxDynamicSharedMemorySize, SMEM_BYTES);

    float *p_feats, *p_lin, *p_ssum, *p_z, *p_logits;
    cudaGetSymbolAddress((void**)&p_feats,  g_feats);
    cudaGetSymbolAddress((void**)&p_lin,    g_lin);
    cudaGetSymbolAddress((void**)&p_ssum,   g_ssum);
    cudaGetSymbolAddress((void**)&p_z,      g_z);
    cudaGetSymbolAddress((void**)&p_logits, g_logits);

    const int* src = ei;        // edge_index[0], E int32
    const int* dst = ei + EE;   // edge_index[1]

    init_feats_k<<<(NN * DIN + 255) / 256, 256, 0, st>>>(x);
    zero_cnt_k<<<(NN + 255) / 256, 256, 0, st>>>();
    count_deg_k<<<(EE + 255) / 256, 256, 0, st>>>(dst);

    for (int l = 0; l < 2; l++) {
        const float* Wm_l = Wm + (size_t)l * RR * DIN * DIN;
        const float* bm_l = bm + (size_t)l * RR * DIN;
        const float* Wa_l = Wa + (size_t)l * RR * 2 * DIN * DIN;
        const float* ba_l = ba + (size_t)l * RR * DIN;

        // lin = feats @ packed(Wm_l)  -> (MPAD, 384)   [launch #4 on l=0: profiled]
        run_mma(p_feats, Wm_l, p_lin, nullptr, NB, 0, 1, 0, DIN, st);
        combine1_k<<<NN, DIN, 0, st>>>(x, bm_l);

        // aggregate over edges -> g_ssum (then averaged in place)
        zero_ssum_k<<<(NN * DIN + 255) / 256, 256, 0, st>>>();
        edge_scatter_k<<<(EE * 32 + 255) / 256, 256, 0, st>>>(src, dst);
        avg_k<<<(NN * DIN + 255) / 256, 256, 0, st>>>();

        // lin2 = feats @ Wa_l[:, 0:128, :] + aggr @ Wa_l[:, 128:256, :]
        run_mma(p_feats, Wa_l, p_lin, nullptr, NB, 0, 1, 0,   2 * DIN, st);
        run_mma(p_ssum,  Wa_l, p_lin, nullptr, NB, 1, 1, DIN, 2 * DIN, st);
        combine2_norm_k<<<NN, DIN, 0, st>>>(x, ba_l);
    }

    // head: z = feats@W1 + b1 (mma) ; logits = z@W2 + b2 (SIMT) ; log_softmax
    run_mma(p_feats, W1, p_z, b1, DIN, 0, 0, 0, DIN, st);
    {
        dim3 grid((DOUT + BN - 1) / BN, MPAD / BM);
        sgemm2_k<<<grid, 256, 0, st>>>(p_z, W2, p_logits, b2, DIN, DOUT, 0);
    }
    logsoftmax_k<<<(NN * 32 + 255) / 256, 256, 0, st>>>(out);
}

// round 16
// speedup vs baseline: 1.7554x; 1.0820x over previous
#include <cuda_runtime.h>
#include <cuda_bf16.h>
#include <math.h>
#include <stdint.h>

#define NN    40000
#define MPAD  40064    // 313 * 128
#define RR    4
#define DIN   128
#define DOUT  40
#define EE    480000
#define XDIM  132      // R + DIN
#define NB    384      // 3 effective roles * 128

#define SA_STR 136     // bf16 elems per A row in smem (128 + 8 pad)
#define SB_STR 136
#define SMEM_BYTES ((2 * 128 * SA_STR + 2 * 128 * SB_STR) * 2)   // 139264

// ---------------- scratch (device globals; no allocation allowed) -------------
__device__ __align__(256) __nv_bfloat16 g_featsH[MPAD * DIN];
__device__ __align__(256) __nv_bfloat16 g_featsL[MPAD * DIN];
__device__ __align__(256) __nv_bfloat16 g_ssumH[MPAD * DIN];
__device__ __align__(256) __nv_bfloat16 g_ssumL[MPAD * DIN];
__device__ __align__(256) float g_lin[MPAD * NB];
__device__ __align__(256) float g_m[NN * DIN];
__device__ __align__(256) float g_ssum[MPAD * DIN];
__device__ __align__(256) float g_cnt[NN];
__device__ __align__(256) float g_z[MPAD * DIN];
__device__ __align__(256) float g_logits[MPAD * DOUT];

// ---------------- warp-mma helpers (baseline PTX, no 'a' features) ------------
__device__ __forceinline__ uint32_t smem_u32(const void* p) {
    uint32_t a;
    asm("{ .reg .u64 t; cvta.to.shared.u64 t, %1; cvt.u32.u64 %0, t; }" : "=r"(a) : "l"(p));
    return a;
}
__device__ __forceinline__ void ldmatrix_x4(uint32_t* r, uint32_t addr) {
    asm volatile("ldmatrix.sync.aligned.m8n8.x4.shared.b16 {%0,%1,%2,%3}, [%4];"
        : "=r"(r[0]), "=r"(r[1]), "=r"(r[2]), "=r"(r[3]) : "r"(addr));
}
__device__ __forceinline__ void mma_bf16(float* d, const uint32_t* a, uint32_t b0, uint32_t b1) {
    asm volatile("mma.sync.aligned.m16n8k16.row.col.f32.bf16.bf16.f32 "
        "{%0,%1,%2,%3}, {%4,%5,%6,%7}, {%8,%9}, {%0,%1,%2,%3};"
        : "+f"(d[0]), "+f"(d[1]), "+f"(d[2]), "+f"(d[3])
        : "r"(a[0]), "r"(a[1]), "r"(a[2]), "r"(a[3]), "r"(b0), "r"(b1));
}

// ================= tensor-core GEMM via mma.sync ==============================
// C(MPAD,Nn) = A(MPAD,128) @ B(128,Nn) (+bias) (+=C).
// A supplied preconverted as bf16 hi/lo arrays; B (fp32 weights) converted in-kernel.
// 3 accumulating passes: Ah*Bh + Al*Bh + Ah*Bl. CTA tile 128x128, 512 threads,
// 16 warps as 4(M) x 4(N), warp tile 32x32. Nn multiple of 128.
// blayout 0: B[k*Nn+col].  blayout 1 (role-packed): W[r][k0w+k][o], r=col>>7, o=col&127.
__global__ void __launch_bounds__(512) mmagemm_k(
    const __nv_bfloat16* __restrict__ AH, const __nv_bfloat16* __restrict__ AL,
    const float* __restrict__ Braw,
    float* __restrict__ C, const float* __restrict__ bias,
    int Nn, int accumulate, int blayout, int k0w, int ktot)
{
    extern __shared__ __nv_bfloat16 sm[];
    __nv_bfloat16* sAh = sm;
    __nv_bfloat16* sAl = sm + 128 * SA_STR;
    __nv_bfloat16* sBh = sm + 2 * 128 * SA_STR;
    __nv_bfloat16* sBl = sm + 2 * 128 * SA_STR + 128 * SB_STR;

    const int tid = threadIdx.x;
    const int bm = blockIdx.y * 128;
    const int bn = blockIdx.x * 128;

    // ---- A tiles: bf16 global -> smem (uint4 = 8 bf16) -------------------
#pragma unroll
    for (int i = tid; i < 2048; i += 512) {
        int row = i >> 4, c8 = (i & 15) << 3;
        int so = row * SA_STR + c8;
        size_t go = (size_t)(bm + row) * 128 + c8;
        *reinterpret_cast<uint4*>(&sAh[so]) = *reinterpret_cast<const uint4*>(&AH[go]);
        *reinterpret_cast<uint4*>(&sAl[so]) = *reinterpret_cast<const uint4*>(&AL[go]);
    }

    // ---- B tile: fp32 gather -> bf16 hi/lo, transposed sBt[n][k] ---------
#pragma unroll 4
    for (int i = tid; i < 16384; i += 512) {
        int k = i >> 7;
        int n = i & 127;
        int col = bn + n;
        float v = (blayout == 0)
            ? Braw[(size_t)k * Nn + col]
            : Braw[((size_t)(col >> 7) * ktot + (k0w + k)) * 128 + (col & 127)];
        __nv_bfloat16 h = __float2bfloat16(v);
        sBh[n * SB_STR + k] = h;
        sBl[n * SB_STR + k] = __float2bfloat16(v - __bfloat162float(h));
    }
    __syncthreads();

    // ---- warp tiles: 16 warps as 4(M) x 4(N), each 32x32 -----------------
    const int w = tid >> 5, lane = tid & 31;
    const int wm = (w & 3) * 32;
    const int wn = (w >> 2) * 32;
    const int mi = lane >> 3, r8 = lane & 7;

    uint32_t aoff = (uint32_t)(((wm + ((mi & 1) << 3) + r8) * SA_STR + ((mi >> 1) << 3)) * 2);
    uint32_t boff = (uint32_t)(((wn + ((mi >> 1) << 3) + r8) * SB_STR + ((mi & 1) << 3)) * 2);
    const uint32_t ASTEP = 16 * SA_STR * 2;
    const uint32_t BSTEP = 16 * SB_STR * 2;

    uint32_t sAh32 = smem_u32(sAh), sAl32 = smem_u32(sAl);
    uint32_t sBh32 = smem_u32(sBh), sBl32 = smem_u32(sBl);

    float acc[2][4][4];
#pragma unroll
    for (int a = 0; a < 2; a++)
#pragma unroll
        for (int b = 0; b < 4; b++)
#pragma unroll
            for (int c = 0; c < 4; c++) acc[a][b][c] = 0.f;

#pragma unroll
    for (int k0 = 0; k0 < 128; k0 += 16) {
        uint32_t Ah0[4], Ah1[4], Al0[4], Al1[4];
        uint32_t Bh0[4], Bh1[4], Bl0[4], Bl1[4];
        ldmatrix_x4(Ah0, sAh32 + aoff + k0 * 2);
        ldmatrix_x4(Ah1, sAh32 + aoff + ASTEP + k0 * 2);
        ldmatrix_x4(Al0, sAl32 + aoff + k0 * 2);
        ldmatrix_x4(Al1, sAl32 + aoff + ASTEP + k0 * 2);
        ldmatrix_x4(Bh0, sBh32 + boff + k0 * 2);
        ldmatrix_x4(Bh1, sBh32 + boff + BSTEP + k0 * 2);
        ldmatrix_x4(Bl0, sBl32 + boff + k0 * 2);
        ldmatrix_x4(Bl1, sBl32 + boff + BSTEP + k0 * 2);
#pragma unroll
        for (int m2 = 0; m2 < 2; m2++) {
            uint32_t* Ah = m2 ? Ah1 : Ah0;
            uint32_t* Al = m2 ? Al1 : Al0;
#pragma unroll
            for (int nf = 0; nf < 4; nf++) {
                uint32_t* Bq = (nf < 2) ? Bh0 : Bh1;
                uint32_t b0 = Bq[(nf & 1) ? 2 : 0];
                uint32_t b1 = Bq[(nf & 1) ? 3 : 1];
                mma_bf16(acc[m2][nf], Ah, b0, b1);   // Ah*Bh
                mma_bf16(acc[m2][nf], Al, b0, b1);   // Al*Bh
                uint32_t* Bl = (nf < 2) ? Bl0 : Bl1;
                uint32_t c0 = Bl[(nf & 1) ? 2 : 0];
                uint32_t c1 = Bl[(nf & 1) ? 3 : 1];
                mma_bf16(acc[m2][nf], Ah, c0, c1);   // Ah*Bl
            }
        }
    }

    // ---- epilogue --------------------------------------------------------
    const int g = lane >> 2, t4 = lane & 3;
#pragma unroll
    for (int m2 = 0; m2 < 2; m2++) {
#pragma unroll
        for (int nf = 0; nf < 4; nf++) {
            int row = bm + wm + m2 * 16 + g;
            int col = bn + wn + nf * 8 + t4 * 2;
            float* c0 = &C[(size_t)row * Nn + col];
            float* c1 = &C[(size_t)(row + 8) * Nn + col];
            float2 v0 = make_float2(acc[m2][nf][0], acc[m2][nf][1]);
            float2 v1 = make_float2(acc[m2][nf][2], acc[m2][nf][3]);
            if (bias) {
                float bb0 = bias[col], bb1 = bias[col + 1];
                v0.x += bb0; v0.y += bb1; v1.x += bb0; v1.y += bb1;
            }
            if (accumulate) {
                float2 o0 = *reinterpret_cast<float2*>(c0);
                float2 o1 = *reinterpret_cast<float2*>(c1);
                v0.x += o0.x; v0.y += o0.y; v1.x += o1.x; v1.y += o1.y;
            }
            *reinterpret_cast<float2*>(c0) = v0;
            *reinterpret_cast<float2*>(c1) = v1;
        }
    }
}

// ---------------- SIMT SGEMM (kept for W2, N=40) ------------------------------
#define BM 128
#define BN 128
#define BK 8
__global__ void __launch_bounds__(256) sgemm2_k(
    const float* __restrict__ A, const float* __restrict__ B,
    float* __restrict__ C, const float* __restrict__ bias,
    int K, int Nn, int accumulate)
{
    __shared__ float As[2][BK][BM];
    __shared__ float Bs[2][BK][BN];
    const int tid = threadIdx.x;
    const int bm = blockIdx.y * BM;
    const int bn = blockIdx.x * BN;
    const int arow = tid >> 1;
    const int acol = (tid & 1) * 4;
    const int brow = tid >> 5;
    const int bcol = (tid & 31) * 4;
    const int trow = (tid >> 4) * 8;
    const int tcol = (tid & 15) * 8;

    float acc[8][8];
#pragma unroll
    for (int i = 0; i < 8; i++)
#pragma unroll
        for (int j = 0; j < 8; j++) acc[i][j] = 0.f;

    const int nk = K / BK;
    {
        float4 a4 = *reinterpret_cast<const float4*>(&A[(size_t)(bm + arow) * K + acol]);
        As[0][acol + 0][arow] = a4.x; As[0][acol + 1][arow] = a4.y;
        As[0][acol + 2][arow] = a4.z; As[0][acol + 3][arow] = a4.w;
        float4 b4 = make_float4(0.f, 0.f, 0.f, 0.f);
        if (bn + bcol < Nn)
            b4 = *reinterpret_cast<const float4*>(&B[(size_t)brow * Nn + bn + bcol]);
        *reinterpret_cast<float4*>(&Bs[0][brow][bcol]) = b4;
    }
    __syncthreads();

    int buf = 0;
    for (int t = 0; t < nk; t++) {
        float4 a4n, b4n;
        if (t + 1 < nk) {
            int kk0 = (t + 1) * BK;
            a4n = *reinterpret_cast<const float4*>(&A[(size_t)(bm + arow) * K + kk0 + acol]);
            b4n = make_float4(0.f, 0.f, 0.f, 0.f);
            if (bn + bcol < Nn)
                b4n = *reinterpret_cast<const float4*>(&B[(size_t)(kk0 + brow) * Nn + bn + bcol]);
        }
#pragma unroll
        for (int kk = 0; kk < BK; kk++) {
            float4 a0 = *reinterpret_cast<const float4*>(&As[buf][kk][trow]);
            float4 a1 = *reinterpret_cast<const float4*>(&As[buf][kk][trow + 4]);
            float4 b0 = *reinterpret_cast<const float4*>(&Bs[buf][kk][tcol]);
            float4 b1 = *reinterpret_cast<const float4*>(&Bs[buf][kk][tcol + 4]);
            float af[8] = {a0.x, a0.y, a0.z, a0.w, a1.x, a1.y, a1.z, a1.w};
            float bf[8] = {b0.x, b0.y, b0.z, b0.w, b1.x, b1.y, b1.z, b1.w};
#pragma unroll
            for (int i = 0; i < 8; i++)
#pragma unroll
                for (int j = 0; j < 8; j++)
                    acc[i][j] += af[i] * bf[j];
        }
        if (t + 1 < nk) {
            int nb = buf ^ 1;
            As[nb][acol + 0][arow] = a4n.x; As[nb][acol + 1][arow] = a4n.y;
            As[nb][acol + 2][arow] = a4n.z; As[nb][acol + 3][arow] = a4n.w;
            *reinterpret_cast<float4*>(&Bs[nb][brow][bcol]) = b4n;
            __syncthreads();
            buf = nb;
        }
    }
#pragma unroll
    for (int i = 0; i < 8; i++) {
        size_t row = (size_t)(bm + trow + i);
#pragma unroll
        for (int j = 0; j < 8; j += 4) {
            int col = bn + tcol + j;
            if (col < Nn) {
                float4 v = make_float4(acc[i][j], acc[i][j + 1], acc[i][j + 2], acc[i][j + 3]);
                if (bias) {
                    v.x += bias[col]; v.y += bias[col + 1];
                    v.z += bias[col + 2]; v.w += bias[col + 3];
                }
                float4* cp = reinterpret_cast<float4*>(&C[row * Nn + col]);
                if (accumulate) {
                    float4 o = *cp;
                    v.x += o.x; v.y += o.y; v.z += o.z; v.w += o.w;
                }
                *cp = v;
            }
        }
    }
}

// ---------------- small/elementwise kernels -----------------------------------
__device__ __forceinline__ void split_bf16(float v, __nv_bfloat16* H, __nv_bfloat16* L, size_t idx) {
    __nv_bfloat16 h = __float2bfloat16(v);
    H[idx] = h;
    L[idx] = __float2bfloat16(v - __bfloat162float(h));
}

__global__ void init_feats_k(const float* __restrict__ x) {
    int idx = blockIdx.x * blockDim.x + threadIdx.x;
    if (idx >= NN * DIN) return;
    int n = idx >> 7, i = idx & 127;
    split_bf16(x[n * XDIM + RR + i], g_featsH, g_featsL, idx);
}
__global__ void zero_cnt_k() {
    int idx = blockIdx.x * blockDim.x + threadIdx.x;
    if (idx < NN) g_cnt[idx] = 0.f;
}
__global__ void count_deg_k(const int* __restrict__ dst) {
    int e = blockIdx.x * blockDim.x + threadIdx.x;
    if (e >= EE) return;
    atomicAdd(&g_cnt[dst[e]], 1.0f);
}
__global__ void combine1_k(const float* __restrict__ x, const float* __restrict__ bm_l) {
    int n = blockIdx.x;
    int o = threadIdx.x;
    float c0 = 2.f * x[n * XDIM + 0];
    float c1 = x[n * XDIM + 1];
    float c2 = x[n * XDIM + 2];
    const float* lp = g_lin + (size_t)n * NB;
    float v = c0 * (lp[o]       + bm_l[o])
            + c1 * (lp[128 + o] + bm_l[128 + o])
            + c2 * (lp[256 + o] + bm_l[256 + o]);
    g_m[(size_t)n * DIN + o] = fmaxf(v, 0.f);
}
__global__ void zero_ssum_k() {
    int idx = blockIdx.x * blockDim.x + threadIdx.x;
    if (idx < NN * DIN) g_ssum[idx] = 0.f;
}
__global__ void edge_scatter_k(const int* __restrict__ src,
                               const int* __restrict__ dst) {
    int gw = (blockIdx.x * blockDim.x + threadIdx.x) >> 5;
    int lane = threadIdx.x & 31;
    if (gw >= EE) return;
    int s = src[gw];
    int d = dst[gw];
    float4 v = *reinterpret_cast<const float4*>(g_m + (size_t)s * DIN + lane * 4);
    float4* p = reinterpret_cast<float4*>(g_ssum + (size_t)d * DIN + lane * 4);
    atomicAdd(p, v);
}
__global__ void avg_k() {
    int idx = blockIdx.x * blockDim.x + threadIdx.x;
    if (idx >= NN * DIN) return;
    int n = idx >> 7;
    float c = g_cnt[n];
    float v = (c > 0.f) ? g_ssum[idx] / c : 0.f;
    split_bf16(v, g_ssumH, g_ssumL, idx);
}
__global__ void combine2_norm_k(const float* __restrict__ x, const float* __restrict__ ba_l) {
    int n = blockIdx.x;
    int o = threadIdx.x;
    float c0 = 2.f * x[n * XDIM + 0];
    float c1 = x[n * XDIM + 1];
    float c2 = x[n * XDIM + 2];
    const float* lp = g_lin + (size_t)n * NB;
    float v = c0 * (lp[o]       + ba_l[o])
            + c1 * (lp[128 + o] + ba_l[128 + o])
            + c2 * (lp[256 + o] + ba_l[256 + o]);
    v = fmaxf(v, 0.f);
    __shared__ float red[4];
    float s = v * v;
#pragma unroll
    for (int off = 16; off; off >>= 1) s += __shfl_xor_sync(0xffffffffu, s, off);
    if ((threadIdx.x & 31) == 0) red[threadIdx.x >> 5] = s;
    __syncthreads();
    float tot = red[0] + red[1] + red[2] + red[3];
    float norm = fmaxf(sqrtf(tot), 1e-12f);
    split_bf16(v / norm, g_featsH, g_featsL, (size_t)n * DIN + o);
}
__global__ void logsoftmax_k(float* __restrict__ out) {
    int n = (blockIdx.x * blockDim.x + threadIdx.x) >> 5;
    int lane = threadIdx.x & 31;
    if (n >= NN) return;
    const float* lp = g_logits + (size_t)n * DOUT;
    float v0 = lp[lane];
    float v1 = (lane < DOUT - 32) ? lp[32 + lane] : -INFINITY;
    float mx = fmaxf(v0, v1);
#pragma unroll
    for (int off = 16; off; off >>= 1) mx = fmaxf(mx, __shfl_xor_sync(0xffffffffu, mx, off));
    float se = expf(v0 - mx) + ((lane < DOUT - 32) ? expf(v1 - mx) : 0.f);
#pragma unroll
    for (int off = 16; off; off >>= 1) se += __shfl_xor_sync(0xffffffffu, se, off);
    float l = mx + logf(se);
    float* op = out + (size_t)n * DOUT;
    op[lane] = v0 - l;
    if (lane < DOUT - 32) op[32 + lane] = v1 - l;
}

// ---------------- host orchestration ------------------------------------------
static inline void run_mma(const __nv_bfloat16* AH, const __nv_bfloat16* AL,
                           const float* Braw, float* C, const float* bias,
                           int Nn, int accumulate, int blayout, int k0, int ktot,
                           cudaStream_t st) {
    dim3 grid(Nn / 128, MPAD / 128);
    mmagemm_k<<<grid, 512, SMEM_BYTES, st>>>(AH, AL, Braw, C, bias, Nn, accumulate, blayout, k0, ktot);
}

extern "C" void kernel_launch(void* const* d_in, const int* in_sizes, int n_in,
                              void* d_out, int out_size) {
    const float* x  = (const float*)d_in[0];
    const int*   ei = (const int*)d_in[1];     // int32 (JAX x64 disabled)
    const float* Wm = (const float*)d_in[2];
    const float* bm = (const float*)d_in[3];
    const float* Wa = (const float*)d_in[4];
    const float* ba = (const float*)d_in[5];
    const float* W1 = (const float*)d_in[6];
    const float* b1 = (const float*)d_in[7];
    const float* W2 = (const float*)d_in[8];
    const float* b2 = (const float*)d_in[9];
    float* out = (float*)d_out;

    cudaStream_t st = 0;

    // idempotent, host-side (safe under graph capture)
    cudaFuncSetAttribute(mmagemm_k, cudaFuncAttributeMaxDynamicSharedMemorySize, SMEM_BYTES);

    float *p_lin, *p_z, *p_logits;
    __nv_bfloat16 *p_fH, *p_fL, *p_sH, *p_sL;
    cudaGetSymbolAddress((void**)&p_lin,    g_lin);
    cudaGetSymbolAddress((void**)&p_z,      g_z);
    cudaGetSymbolAddress((void**)&p_logits, g_logits);
    cudaGetSymbolAddress((void**)&p_fH,     g_featsH);
    cudaGetSymbolAddress((void**)&p_fL,     g_featsL);
    cudaGetSymbolAddress((void**)&p_sH,     g_ssumH);
    cudaGetSymbolAddress((void**)&p_sL,     g_ssumL);

    const int* src = ei;        // edge_index[0], E int32
    const int* dst = ei + EE;   // edge_index[1]

    init_feats_k<<<(NN * DIN + 255) / 256, 256, 0, st>>>(x);
    zero_cnt_k<<<(NN + 255) / 256, 256, 0, st>>>();
    count_deg_k<<<(EE + 255) / 256, 256, 0, st>>>(dst);

    for (int l = 0; l < 2; l++) {
        const float* Wm_l = Wm + (size_t)l * RR * DIN * DIN;
        const float* bm_l = bm + (size_t)l * RR * DIN;
        const float* Wa_l = Wa + (size_t)l * RR * 2 * DIN * DIN;
        const float* ba_l = ba + (size_t)l * RR * DIN;

        // lin = feats @ packed(Wm_l)  -> (MPAD, 384)   [launch #4 on l=0: profiled]
        run_mma(p_fH, p_fL, Wm_l, p_lin, nullptr, NB, 0, 1, 0, DIN, st);
        combine1_k<<<NN, DIN, 0, st>>>(x, bm_l);

        // aggregate over edges -> g_ssum, then average + bf16-split
        zero_ssum_k<<<(NN * DIN + 255) / 256, 256, 0, st>>>();
        edge_scatter_k<<<(EE * 32 + 255) / 256, 256, 0, st>>>(src, dst);
        avg_k<<<(NN * DIN + 255) / 256, 256, 0, st>>>();

        // lin2 = feats @ Wa_l[:, 0:128, :] + aggr @ Wa_l[:, 128:256, :]
        run_mma(p_fH, p_fL, Wa_l, p_lin, nullptr, NB, 0, 1, 0,   2 * DIN, st);
        run_mma(p_sH, p_sL, Wa_l, p_lin, nullptr, NB, 1, 1, DIN, 2 * DIN, st);
        combine2_norm_k<<<NN, DIN, 0, st>>>(x, ba_l);
    }

    // head: z = feats@W1 + b1 (mma) ; logits = z@W2 + b2 (SIMT) ; log_softmax
    run_mma(p_fH, p_fL, W1, p_z, b1, DIN, 0, 0, 0, DIN, st);
    {
        dim3 grid((DOUT + BN - 1) / BN, MPAD / BM);
        sgemm2_k<<<grid, 256, 0, st>>>(p_z, W2, p_logits, b2, DIN, DOUT, 0);
    }
    logsoftmax_k<<<(NN * 32 + 255) / 256, 256, 0, st>>>(out);
}